// round 13
// baseline (speedup 1.0000x reference)
#include <cuda_runtime.h>
#include <cuda_fp16.h>
#include <math.h>
#include <stdint.h>

#define NB 4
#define NS 2048
#define ND 1024
#define NH 16
#define HDIM 64
#define NM (NB*NS)
#define MM (ND*ND)

// fp16 scratch (~58 MB), all k'-interleaved per 32-block:
//   k = 16u+8v+2t+w  ->  k' = 8t+4u+2v+w
// g_XP/g_WP/g_AO: [row][1024]
// g_Q: [bh][s][64]  (pre-scaled by 0.125, d interleaved)
// g_K: [bh][key][64] (d interleaved)
// g_V: [bh][d][2048] (key interleaved)
__device__ __align__(256) __half g_Q [(size_t)NB*NH*NS*HDIM];
__device__ __align__(256) __half g_K [(size_t)NB*NH*NS*HDIM];
__device__ __align__(256) __half g_V [(size_t)NB*NH*NS*HDIM];
__device__ __align__(256) __half g_AO[(size_t)NM*ND];
__device__ __align__(256) __half g_XP[(size_t)NM*ND];
__device__ __align__(256) __half g_WP[(size_t)4*MM];

__device__ __forceinline__ void mma_f16(float d[4], uint32_t a0, uint32_t a1,
                                        uint32_t a2, uint32_t a3,
                                        uint32_t b0, uint32_t b1) {
    asm volatile(
        "mma.sync.aligned.m16n8k16.row.col.f32.f16.f16.f32 "
        "{%0,%1,%2,%3},{%4,%5,%6,%7},{%8,%9},{%0,%1,%2,%3};"
        : "+f"(d[0]), "+f"(d[1]), "+f"(d[2]), "+f"(d[3])
        : "r"(a0), "r"(a1), "r"(a2), "r"(a3), "r"(b0), "r"(b1));
}
__device__ __forceinline__ uint32_t h2u(float a, float b) {
    __half2 h = __halves2half2(__float2half_rn(a), __float2half_rn(b));
    return *(uint32_t*)&h;
}
__device__ __forceinline__ int kpos(int k) {
    return (k & ~31) | (8*((k>>1)&3) + 4*((k>>4)&1) + 2*((k>>3)&1) + (k&1));
}
__device__ __forceinline__ void cp16(void* dst, const void* src) {
    uint32_t d = (uint32_t)__cvta_generic_to_shared(dst);
    asm volatile("cp.async.cg.shared.global [%0], [%1], 16;" :: "r"(d), "l"(src));
}
__device__ __forceinline__ void cp_commit() {
    asm volatile("cp.async.commit_group;" ::: "memory");
}
__device__ __forceinline__ void cp_wait0() {
    asm volatile("cp.async.wait_group 0;" ::: "memory");
}
__device__ __forceinline__ void cp_wait1() {
    asm volatile("cp.async.wait_group 1;" ::: "memory");
}

// ---------------------------------------------------------------------------
// Prep: fp16-round x and 4 weights into k'-interleaved layout.
// ---------------------------------------------------------------------------
__global__ __launch_bounds__(256) void prep(
    const float* __restrict__ x,
    const float* __restrict__ wq, const float* __restrict__ wk,
    const float* __restrict__ wv, const float* __restrict__ wo)
{
    const size_t XC = (size_t)NM * 128;
    const size_t WC = (size_t)ND * 128;
    size_t i = (size_t)blockIdx.x * 256 + threadIdx.x;
    const float* src; __half* dst; size_t o;
    if (i < XC) { src = x; dst = g_XP; o = i; }
    else if (i < XC + 4 * WC) {
        size_t j = i - XC;
        int w = (int)(j / WC);
        o = j - (size_t)w * WC;
        src = (w == 0) ? wq : (w == 1) ? wk : (w == 2) ? wv : wo;
        dst = g_WP + (size_t)w * MM;
    } else return;
    size_t row = o >> 7;
    int c = (int)(o & 127), blk = c >> 2, t = c & 3;
    const float* s = src + row * ND + blk * 32 + 2 * t;
    uint4 v;
    v.x = h2u(s[0],  s[1]);
    v.y = h2u(s[8],  s[9]);
    v.z = h2u(s[16], s[17]);
    v.w = h2u(s[24], s[25]);
    *(uint4*)(dst + row * ND + blk * 32 + t * 8) = v;
}

// ---------------------------------------------------------------------------
// C = A @ W^T + bias, fp16 m16n8k16.  (R11 shape — best measured GEMM.)
// CTA 128x128x64, 4 warps (2m x 2n), warp 64x64, 3-stage cp.async ring.
// 128 thr, 2 CTAs/SM.
// ---------------------------------------------------------------------------
#define STG_H 16384                 // halves per stage (A 8192 + B 8192)
#define GEMM_SMEM (3*STG_H*2)       // 98304 B

__global__ __launch_bounds__(128, 2) void gemm_f16(
    const float* __restrict__ bq, const float* __restrict__ bk,
    const float* __restrict__ bv, float* __restrict__ Cout,
    int amode, int fused, int cmode0)
{
    extern __shared__ __half smh[];
    const __half* A = amode ? g_AO : g_XP;
    int sel, nblk, cmode;
    const float* bias;
    if (fused) {
        sel  = blockIdx.x >> 3;
        nblk = blockIdx.x & 7;
        bias = (sel == 0) ? bq : (sel == 1) ? bk : bv;
        cmode = sel + 1;
    } else { sel = 3; nblk = blockIdx.x; bias = bq; cmode = cmode0; }
    const __half* W = g_WP + (size_t)sel * MM;

    const int tid = threadIdx.x, lane = tid & 31, wid = tid >> 5;
    const int wm = wid & 1, wn = wid >> 1;
    const int m0 = blockIdx.y * 128, n0 = nblk * 128;
    const int g = lane >> 2, t = lane & 3;

    float acc[4][8][4];
#pragma unroll
    for (int i = 0; i < 4; i++)
#pragma unroll
        for (int j = 0; j < 8; j++)
#pragma unroll
            for (int c = 0; c < 4; c++) acc[i][j][c] = 0.0f;

    const __half* Ap = A + (size_t)m0 * ND;
    const __half* Wp = W + (size_t)n0 * ND;

    auto loadStage = [&](int c) {
        __half* As = smh + (c % 3) * STG_H;
        __half* Bs = As + 8192;
#pragma unroll
        for (int i = 0; i < 8; i++) {
            int f = tid + i * 128;           // 0..1023
            int row = f >> 3, q = f & 7;
            int sub = q >> 2, qq = q & 3;
            cp16(As + sub * 4096 + row * 32 + qq * 8,
                 Ap + (size_t)row * ND + c * 64 + sub * 32 + qq * 8);
            cp16(Bs + sub * 4096 + row * 32 + qq * 8,
                 Wp + (size_t)row * ND + c * 64 + sub * 32 + qq * 8);
        }
    };

    loadStage(0); cp_commit();
    loadStage(1); cp_commit();

    for (int c = 0; c < 16; c++) {
        if (c + 1 < 16) cp_wait1(); else cp_wait0();
        __syncthreads();
        if (c + 2 < 16) { loadStage(c + 2); cp_commit(); }

#pragma unroll
        for (int b = 0; b < 2; b++) {
            const __half* As = smh + (c % 3) * STG_H + b * 4096;
            const __half* Bs = As + 8192;

            uint4 alo[4], ahi[4];
#pragma unroll
            for (int mi = 0; mi < 4; mi++) {
                int r = wm * 64 + mi * 16 + g;
                alo[mi] = *(const uint4*)(As + r * 32 + t * 8);
                ahi[mi] = *(const uint4*)(As + (r + 8) * 32 + t * 8);
            }
            uint4 bv4[8];
#pragma unroll
            for (int ni = 0; ni < 8; ni++)
                bv4[ni] = *(const uint4*)(Bs + (wn * 64 + ni * 8 + g) * 32 + t * 8);

#pragma unroll
            for (int mi = 0; mi < 4; mi++)
#pragma unroll
                for (int ni = 0; ni < 8; ni++)
                    mma_f16(acc[mi][ni], alo[mi].x, ahi[mi].x, alo[mi].y,
                            ahi[mi].y, bv4[ni].x, bv4[ni].y);
#pragma unroll
            for (int mi = 0; mi < 4; mi++)
#pragma unroll
                for (int ni = 0; ni < 8; ni++)
                    mma_f16(acc[mi][ni], alo[mi].z, ahi[mi].z, alo[mi].w,
                            ahi[mi].w, bv4[ni].z, bv4[ni].w);
        }
    }

    // ---- epilogue ----
#pragma unroll
    for (int mi = 0; mi < 4; mi++) {
#pragma unroll
        for (int ni = 0; ni < 8; ni++) {
            int mlo = m0 + wm * 64 + mi * 16 + g;
            int n = n0 + wn * 64 + ni * 8 + 2 * t;
            float2 bl = *(const float2*)&bias[n];
            float cc[4] = { acc[mi][ni][0] + bl.x, acc[mi][ni][1] + bl.y,
                            acc[mi][ni][2] + bl.x, acc[mi][ni][3] + bl.y };
            if (cmode == 0) {
                *(float2*)&Cout[(size_t)mlo * ND + n] = make_float2(cc[0], cc[1]);
                *(float2*)&Cout[(size_t)(mlo + 8) * ND + n] = make_float2(cc[2], cc[3]);
            } else {
                int h = n >> 6, hd = n & 63;
#pragma unroll
                for (int rr = 0; rr < 2; rr++) {
                    int m = mlo + 8 * rr;
                    int bb = m >> 11, ss = m & 2047;
                    int bhh = bb * NH + h;
                    float ca = cc[2 * rr], cb = cc[2 * rr + 1];
                    if (cmode == 1) {
                        __half2 hv = __halves2half2(__float2half_rn(ca * 0.125f),
                                                    __float2half_rn(cb * 0.125f));
                        *(__half2*)&g_Q[((size_t)bhh * NS + ss) * HDIM + kpos(hd)] = hv;
                    } else if (cmode == 2) {
                        __half2 hv = __halves2half2(__float2half_rn(ca),
                                                    __float2half_rn(cb));
                        *(__half2*)&g_K[((size_t)bhh * NS + ss) * HDIM + kpos(hd)] = hv;
                    } else {
                        int p = kpos(ss);
                        g_V[((size_t)bhh * HDIM + hd) * NS + p] = __float2half_rn(ca);
                        g_V[((size_t)bhh * HDIM + hd + 1) * NS + p] = __float2half_rn(cb);
                    }
                }
            }
        }
    }
}

// ---------------------------------------------------------------------------
// fp16 flash attention, causal. CTA: 128 q-rows of one (b,h); 8 warps,
// warp owns ONE m16 tile. 256 thr, 2 CTAs/SM.
// Buffers now hold 128 keys (two 64-key sub-tiles) -> barriers halved.
// ---------------------------------------------------------------------------
#define FLASH_SMEM 65536   // 2 x (K 8192h + V 8192h) x 2B

__global__ __launch_bounds__(256, 2) void flash_attn_f16()
{
    extern __shared__ __half smf[];
    const int tid = threadIdx.x, lane = tid & 31, wq = tid >> 5;
    const int g = lane >> 2, t = lane & 3;
    const int bh = blockIdx.y;
    const int qt = (int)gridDim.x - 1 - (int)blockIdx.x;
    const int q0 = qt * 128;
    const int trow = q0 + wq * 16;
    const int xorsw = (g & 1) << 2;

    const __half* Kb = g_K + (size_t)bh * NS * HDIM;
    const __half* Vb = g_V + (size_t)bh * HDIM * NS;

    // ---- Q fragments (direct from global; 4 LDG.128) ----
    uint32_t qf[4][4];
    {
        const __half* p0 = g_Q + ((size_t)bh * NS + trow + g) * HDIM;
        const __half* p1 = g_Q + ((size_t)bh * NS + trow + g + 8) * HDIM;
        uint4 a0 = *(const uint4*)(p0 + t * 8);
        uint4 a1 = *(const uint4*)(p1 + t * 8);
        uint4 b0 = *(const uint4*)(p0 + 32 + t * 8);
        uint4 b1 = *(const uint4*)(p1 + 32 + t * 8);
        qf[0][0]=a0.x; qf[0][1]=a1.x; qf[0][2]=a0.y; qf[0][3]=a1.y;
        qf[1][0]=a0.z; qf[1][1]=a1.z; qf[1][2]=a0.w; qf[1][3]=a1.w;
        qf[2][0]=b0.x; qf[2][1]=b1.x; qf[2][2]=b0.y; qf[2][3]=b1.y;
        qf[3][0]=b0.z; qf[3][1]=b1.z; qf[3][2]=b0.w; qf[3][3]=b1.w;
    }

    // prefetch one 128-key block (two 64-key sub-tiles for K and V)
    auto prefetch = [&](int kt2) {
        __half* Ks = smf + (kt2 & 1) * 8192;
        __half* Vs = smf + 16384 + (kt2 & 1) * 8192;
        int kk0 = kt2 * 128;
        // K: 128 key-rows x 64 d  (sub-tile = key>>6)
#pragma unroll
        for (int i = 0; i < 4; i++) {
            int cid = tid + i * 256;          // 0..1023
            int row = cid >> 3, c = cid & 7;  // row=key 0..127
            int sub = row >> 6, r64 = row & 63;
            int sw = c ^ ((r64 & 1) << 2);
            cp16(Ks + sub * 4096 + r64 * 64 + sw * 8,
                 Kb + (size_t)(kk0 + row) * HDIM + c * 8);
        }
        // V: 64 d-rows x 128 keys  (sub-tile = keychunk>>3)
#pragma unroll
        for (int i = 0; i < 4; i++) {
            int cid = tid + i * 256;           // 0..1023
            int d = cid >> 4, c = cid & 15;    // c = 8-key chunk 0..15
            int sub = c >> 3, cc = c & 7;
            int sw = cc ^ ((d & 1) << 2);
            cp16(Vs + sub * 4096 + d * 64 + sw * 8,
                 Vb + (size_t)d * NS + kk0 + c * 8);
        }
    };

    prefetch(0); cp_commit();

    float oacc[8][4];
#pragma unroll
    for (int i = 0; i < 8; i++)
#pragma unroll
        for (int c = 0; c < 4; c++) oacc[i][c] = 0.0f;
    float mx0 = -INFINITY, mx1 = -INFINITY;
    float ls0 = 0.0f, ls1 = 0.0f;

    const int kt2max = qt;                 // 128-key tiles 0..qt
    for (int kt2 = 0; kt2 <= kt2max; kt2++) {
        cp_wait0();
        __syncthreads();
        if (kt2 < kt2max) { prefetch(kt2 + 1); cp_commit(); }

#pragma unroll
        for (int hh = 0; hh < 2; hh++) {
            const int k0 = kt2 * 128 + hh * 64;
            if (k0 > trow + 15) continue;  // warp-uniform
            const __half* Ks = smf + (kt2 & 1) * 8192 + hh * 4096;
            const __half* Vs = smf + 16384 + (kt2 & 1) * 8192 + hh * 4096;

            // ---- S = Q K^T (k-step outer) ----
            float sacc[8][4];
#pragma unroll
            for (int i = 0; i < 8; i++)
#pragma unroll
                for (int c = 0; c < 4; c++) sacc[i][c] = 0.0f;

#pragma unroll
            for (int nth = 0; nth < 2; nth++) {
                uint4 kb[4][2];
#pragma unroll
                for (int j = 0; j < 4; j++) {
                    const __half* rb = Ks + (8 * (nth * 4 + j) + g) * 64;
                    kb[j][0] = *(const uint4*)(rb + (t ^ xorsw) * 8);
                    kb[j][1] = *(const uint4*)(rb + ((4 + t) ^ xorsw) * 8);
                }
#pragma unroll
                for (int s = 0; s < 4; s++)
#pragma unroll
                    for (int j = 0; j < 4; j++) {
                        int nt = nth * 4 + j;
                        uint32_t b0 = (s & 1) ? kb[j][s >> 1].z : kb[j][s >> 1].x;
                        uint32_t b1 = (s & 1) ? kb[j][s >> 1].w : kb[j][s >> 1].y;
                        mma_f16(sacc[nt], qf[s][0], qf[s][1], qf[s][2], qf[s][3],
                                b0, b1);
                    }
            }

            // ---- causal mask + online softmax + register P pack ----
            if (k0 + 63 > trow) {
                int r0 = trow + g, r1 = r0 + 8;
#pragma unroll
                for (int nt = 0; nt < 8; nt++) {
                    int c0 = k0 + 8 * nt + 2 * t;
                    if (c0     > r0) sacc[nt][0] = -INFINITY;
                    if (c0 + 1 > r0) sacc[nt][1] = -INFINITY;
                    if (c0     > r1) sacc[nt][2] = -INFINITY;
                    if (c0 + 1 > r1) sacc[nt][3] = -INFINITY;
                }
            }
            float t0 = -INFINITY, t1 = -INFINITY;
#pragma unroll
            for (int nt = 0; nt < 8; nt++) {
                t0 = fmaxf(t0, fmaxf(sacc[nt][0], sacc[nt][1]));
                t1 = fmaxf(t1, fmaxf(sacc[nt][2], sacc[nt][3]));
            }
            t0 = fmaxf(t0, __shfl_xor_sync(0xffffffffu, t0, 1));
            t0 = fmaxf(t0, __shfl_xor_sync(0xffffffffu, t0, 2));
            t1 = fmaxf(t1, __shfl_xor_sync(0xffffffffu, t1, 1));
            t1 = fmaxf(t1, __shfl_xor_sync(0xffffffffu, t1, 2));
            float nm0 = fmaxf(mx0, t0), nm1 = fmaxf(mx1, t1);
            float corr0 = __expf(mx0 - nm0), corr1 = __expf(mx1 - nm1);

            float ps0 = 0.0f, ps1 = 0.0f;
#pragma unroll
            for (int nt = 0; nt < 8; nt++) {
                float p0 = __expf(sacc[nt][0] - nm0);
                float p1 = __expf(sacc[nt][1] - nm0);
                float p2 = __expf(sacc[nt][2] - nm1);
                float p3 = __expf(sacc[nt][3] - nm1);
                ps0 += p0 + p1; ps1 += p2 + p3;
                sacc[nt][0] = p0; sacc[nt][1] = p1;
                sacc[nt][2] = p2; sacc[nt][3] = p3;
            }
            ps0 += __shfl_xor_sync(0xffffffffu, ps0, 1);
            ps0 += __shfl_xor_sync(0xffffffffu, ps0, 2);
            ps1 += __shfl_xor_sync(0xffffffffu, ps1, 1);
            ps1 += __shfl_xor_sync(0xffffffffu, ps1, 2);
            ls0 = ls0 * corr0 + ps0;
            ls1 = ls1 * corr1 + ps1;
            mx0 = nm0; mx1 = nm1;
#pragma unroll
            for (int nt = 0; nt < 8; nt++) {
                oacc[nt][0] *= corr0; oacc[nt][1] *= corr0;
                oacc[nt][2] *= corr1; oacc[nt][3] *= corr1;
            }
            uint32_t pf[4][4];
#pragma unroll
            for (int s = 0; s < 4; s++) {
                pf[s][0] = h2u(sacc[2*s][0],   sacc[2*s][1]);
                pf[s][1] = h2u(sacc[2*s][2],   sacc[2*s][3]);
                pf[s][2] = h2u(sacc[2*s+1][0], sacc[2*s+1][1]);
                pf[s][3] = h2u(sacc[2*s+1][2], sacc[2*s+1][3]);
            }

            // ---- O += P V (k-step outer) ----
#pragma unroll
            for (int nth = 0; nth < 2; nth++) {
                uint4 vb[4][2];
#pragma unroll
                for (int j = 0; j < 4; j++) {
                    const __half* rb = Vs + (8 * (nth * 4 + j) + g) * 64;
                    vb[j][0] = *(const uint4*)(rb + (t ^ xorsw) * 8);
                    vb[j][1] = *(const uint4*)(rb + ((4 + t) ^ xorsw) * 8);
                }
#pragma unroll
                for (int s = 0; s < 4; s++)
#pragma unroll
                    for (int j = 0; j < 4; j++) {
                        int nt = nth * 4 + j;
                        uint32_t b0 = (s & 1) ? vb[j][s >> 1].z : vb[j][s >> 1].x;
                        uint32_t b1 = (s & 1) ? vb[j][s >> 1].w : vb[j][s >> 1].y;
                        mma_f16(oacc[nt], pf[s][0], pf[s][1], pf[s][2], pf[s][3],
                                b0, b1);
                    }
            }
        }
    }

    // ---- epilogue: fp16 k'-interleaved g_AO ----
    int b = bh >> 4, h = bh & 15;
    float inv0 = 1.0f / ls0, inv1 = 1.0f / ls1;
    int row0 = trow + g;
    __half* O0 = g_AO + ((size_t)(b * NS + row0)) * ND + h * HDIM;
    __half* O1 = g_AO + ((size_t)(b * NS + row0 + 8)) * ND + h * HDIM;
#pragma unroll
    for (int nt = 0; nt < 8; nt++) {
        int p = kpos(8 * nt + 2 * t);
        *(__half2*)&O0[p] = __halves2half2(
            __float2half_rn(oacc[nt][0] * inv0),
            __float2half_rn(oacc[nt][1] * inv0));
        *(__half2*)&O1[p] = __halves2half2(
            __float2half_rn(oacc[nt][2] * inv1),
            __float2half_rn(oacc[nt][3] * inv1));
    }
}

// ---------------------------------------------------------------------------
extern "C" void kernel_launch(void* const* d_in, const int* in_sizes, int n_in,
                              void* d_out, int out_size)
{
    const float* x    = (const float*)d_in[0];
    const float* wq_w = (const float*)d_in[1];
    const float* wq_b = (const float*)d_in[2];
    const float* wk_w = (const float*)d_in[3];
    const float* wk_b = (const float*)d_in[4];
    const float* wv_w = (const float*)d_in[5];
    const float* wv_b = (const float*)d_in[6];
    const float* wo_w = (const float*)d_in[7];
    const float* wo_b = (const float*)d_in[8];
    float* out = (float*)d_out;

    cudaFuncSetAttribute(gemm_f16, cudaFuncAttributeMaxDynamicSharedMemorySize,
                         GEMM_SMEM);
    cudaFuncSetAttribute(flash_attn_f16,
                         cudaFuncAttributeMaxDynamicSharedMemorySize, FLASH_SMEM);

    prep<<<6144, 256>>>(x, wq_w, wk_w, wv_w, wo_w);

    gemm_f16<<<dim3(24, NM / 128), 128, GEMM_SMEM>>>(
        wq_b, wk_b, wv_b, nullptr, 0, 1, 0);

    flash_attn_f16<<<dim3(NS / 128, NB * NH), 256, FLASH_SMEM>>>();

    gemm_f16<<<dim3(8, NM / 128), 128, GEMM_SMEM>>>(
        wo_b, nullptr, nullptr, out, 1, 0, 0);
}

// round 14
// speedup vs baseline: 1.0115x; 1.0115x over previous
#include <cuda_runtime.h>
#include <cuda_fp16.h>
#include <math.h>
#include <stdint.h>

#define NB 4
#define NS 2048
#define ND 1024
#define NH 16
#define HDIM 64
#define NM (NB*NS)
#define MM (ND*ND)

// fp16 scratch (~58 MB), all k'-interleaved per 32-block:
//   k = 16u+8v+2t+w  ->  k' = 8t+4u+2v+w
// g_XP/g_WP/g_AO: [row][1024]
// g_Q: [bh][s][64]  (pre-scaled by 0.125, d interleaved)
// g_K: [bh][key][64] (d interleaved)
// g_V: [bh][d][2048] (key interleaved)
__device__ __align__(256) __half g_Q [(size_t)NB*NH*NS*HDIM];
__device__ __align__(256) __half g_K [(size_t)NB*NH*NS*HDIM];
__device__ __align__(256) __half g_V [(size_t)NB*NH*NS*HDIM];
__device__ __align__(256) __half g_AO[(size_t)NM*ND];
__device__ __align__(256) __half g_XP[(size_t)NM*ND];
__device__ __align__(256) __half g_WP[(size_t)4*MM];

__device__ __forceinline__ void mma_f16(float d[4], uint32_t a0, uint32_t a1,
                                        uint32_t a2, uint32_t a3,
                                        uint32_t b0, uint32_t b1) {
    asm volatile(
        "mma.sync.aligned.m16n8k16.row.col.f32.f16.f16.f32 "
        "{%0,%1,%2,%3},{%4,%5,%6,%7},{%8,%9},{%0,%1,%2,%3};"
        : "+f"(d[0]), "+f"(d[1]), "+f"(d[2]), "+f"(d[3])
        : "r"(a0), "r"(a1), "r"(a2), "r"(a3), "r"(b0), "r"(b1));
}
__device__ __forceinline__ uint32_t h2u(float a, float b) {
    __half2 h = __halves2half2(__float2half_rn(a), __float2half_rn(b));
    return *(uint32_t*)&h;
}
__device__ __forceinline__ int kpos(int k) {
    return (k & ~31) | (8*((k>>1)&3) + 4*((k>>4)&1) + 2*((k>>3)&1) + (k&1));
}
__device__ __forceinline__ void cp16(void* dst, const void* src) {
    uint32_t d = (uint32_t)__cvta_generic_to_shared(dst);
    asm volatile("cp.async.cg.shared.global [%0], [%1], 16;" :: "r"(d), "l"(src));
}
__device__ __forceinline__ void cp_commit() {
    asm volatile("cp.async.commit_group;" ::: "memory");
}
__device__ __forceinline__ void cp_wait0() {
    asm volatile("cp.async.wait_group 0;" ::: "memory");
}
__device__ __forceinline__ void cp_wait1() {
    asm volatile("cp.async.wait_group 1;" ::: "memory");
}

// ---------------------------------------------------------------------------
// Prep: fp16-round x and 4 weights into k'-interleaved layout.
// ---------------------------------------------------------------------------
__global__ __launch_bounds__(256) void prep(
    const float* __restrict__ x,
    const float* __restrict__ wq, const float* __restrict__ wk,
    const float* __restrict__ wv, const float* __restrict__ wo)
{
    const size_t XC = (size_t)NM * 128;
    const size_t WC = (size_t)ND * 128;
    size_t i = (size_t)blockIdx.x * 256 + threadIdx.x;
    const float* src; __half* dst; size_t o;
    if (i < XC) { src = x; dst = g_XP; o = i; }
    else if (i < XC + 4 * WC) {
        size_t j = i - XC;
        int w = (int)(j / WC);
        o = j - (size_t)w * WC;
        src = (w == 0) ? wq : (w == 1) ? wk : (w == 2) ? wv : wo;
        dst = g_WP + (size_t)w * MM;
    } else return;
    size_t row = o >> 7;
    int c = (int)(o & 127), blk = c >> 2, t = c & 3;
    const float* s = src + row * ND + blk * 32 + 2 * t;
    uint4 v;
    v.x = h2u(s[0],  s[1]);
    v.y = h2u(s[8],  s[9]);
    v.z = h2u(s[16], s[17]);
    v.w = h2u(s[24], s[25]);
    *(uint4*)(dst + row * ND + blk * 32 + t * 8) = v;
}

// ---------------------------------------------------------------------------
// C = A @ W^T + bias, fp16 m16n8k16.  (R11/R13 shape — best measured GEMM.)
// CTA 128x128x64, 4 warps (2m x 2n), warp 64x64, 3-stage cp.async ring.
// 128 thr, 2 CTAs/SM.
// ---------------------------------------------------------------------------
#define STG_H 16384                 // halves per stage (A 8192 + B 8192)
#define GEMM_SMEM (3*STG_H*2)       // 98304 B

__global__ __launch_bounds__(128, 2) void gemm_f16(
    const float* __restrict__ bq, const float* __restrict__ bk,
    const float* __restrict__ bv, float* __restrict__ Cout,
    int amode, int fused, int cmode0)
{
    extern __shared__ __half smh[];
    const __half* A = amode ? g_AO : g_XP;
    int sel, nblk, cmode;
    const float* bias;
    if (fused) {
        sel  = blockIdx.x >> 3;
        nblk = blockIdx.x & 7;
        bias = (sel == 0) ? bq : (sel == 1) ? bk : bv;
        cmode = sel + 1;
    } else { sel = 3; nblk = blockIdx.x; bias = bq; cmode = cmode0; }
    const __half* W = g_WP + (size_t)sel * MM;

    const int tid = threadIdx.x, lane = tid & 31, wid = tid >> 5;
    const int wm = wid & 1, wn = wid >> 1;
    const int m0 = blockIdx.y * 128, n0 = nblk * 128;
    const int g = lane >> 2, t = lane & 3;

    float acc[4][8][4];
#pragma unroll
    for (int i = 0; i < 4; i++)
#pragma unroll
        for (int j = 0; j < 8; j++)
#pragma unroll
            for (int c = 0; c < 4; c++) acc[i][j][c] = 0.0f;

    const __half* Ap = A + (size_t)m0 * ND;
    const __half* Wp = W + (size_t)n0 * ND;

    auto loadStage = [&](int c) {
        __half* As = smh + (c % 3) * STG_H;
        __half* Bs = As + 8192;
#pragma unroll
        for (int i = 0; i < 8; i++) {
            int f = tid + i * 128;           // 0..1023
            int row = f >> 3, q = f & 7;
            int sub = q >> 2, qq = q & 3;
            cp16(As + sub * 4096 + row * 32 + qq * 8,
                 Ap + (size_t)row * ND + c * 64 + sub * 32 + qq * 8);
            cp16(Bs + sub * 4096 + row * 32 + qq * 8,
                 Wp + (size_t)row * ND + c * 64 + sub * 32 + qq * 8);
        }
    };

    loadStage(0); cp_commit();
    loadStage(1); cp_commit();

    for (int c = 0; c < 16; c++) {
        if (c + 1 < 16) cp_wait1(); else cp_wait0();
        __syncthreads();
        if (c + 2 < 16) { loadStage(c + 2); cp_commit(); }

#pragma unroll
        for (int b = 0; b < 2; b++) {
            const __half* As = smh + (c % 3) * STG_H + b * 4096;
            const __half* Bs = As + 8192;

            uint4 alo[4], ahi[4];
#pragma unroll
            for (int mi = 0; mi < 4; mi++) {
                int r = wm * 64 + mi * 16 + g;
                alo[mi] = *(const uint4*)(As + r * 32 + t * 8);
                ahi[mi] = *(const uint4*)(As + (r + 8) * 32 + t * 8);
            }
            uint4 bv4[8];
#pragma unroll
            for (int ni = 0; ni < 8; ni++)
                bv4[ni] = *(const uint4*)(Bs + (wn * 64 + ni * 8 + g) * 32 + t * 8);

#pragma unroll
            for (int mi = 0; mi < 4; mi++)
#pragma unroll
                for (int ni = 0; ni < 8; ni++)
                    mma_f16(acc[mi][ni], alo[mi].x, ahi[mi].x, alo[mi].y,
                            ahi[mi].y, bv4[ni].x, bv4[ni].y);
#pragma unroll
            for (int mi = 0; mi < 4; mi++)
#pragma unroll
                for (int ni = 0; ni < 8; ni++)
                    mma_f16(acc[mi][ni], alo[mi].z, ahi[mi].z, alo[mi].w,
                            ahi[mi].w, bv4[ni].z, bv4[ni].w);
        }
    }

    // ---- epilogue ----
#pragma unroll
    for (int mi = 0; mi < 4; mi++) {
#pragma unroll
        for (int ni = 0; ni < 8; ni++) {
            int mlo = m0 + wm * 64 + mi * 16 + g;
            int n = n0 + wn * 64 + ni * 8 + 2 * t;
            float2 bl = *(const float2*)&bias[n];
            float cc[4] = { acc[mi][ni][0] + bl.x, acc[mi][ni][1] + bl.y,
                            acc[mi][ni][2] + bl.x, acc[mi][ni][3] + bl.y };
            if (cmode == 0) {
                *(float2*)&Cout[(size_t)mlo * ND + n] = make_float2(cc[0], cc[1]);
                *(float2*)&Cout[(size_t)(mlo + 8) * ND + n] = make_float2(cc[2], cc[3]);
            } else {
                int h = n >> 6, hd = n & 63;
#pragma unroll
                for (int rr = 0; rr < 2; rr++) {
                    int m = mlo + 8 * rr;
                    int bb = m >> 11, ss = m & 2047;
                    int bhh = bb * NH + h;
                    float ca = cc[2 * rr], cb = cc[2 * rr + 1];
                    if (cmode == 1) {
                        __half2 hv = __halves2half2(__float2half_rn(ca * 0.125f),
                                                    __float2half_rn(cb * 0.125f));
                        *(__half2*)&g_Q[((size_t)bhh * NS + ss) * HDIM + kpos(hd)] = hv;
                    } else if (cmode == 2) {
                        __half2 hv = __halves2half2(__float2half_rn(ca),
                                                    __float2half_rn(cb));
                        *(__half2*)&g_K[((size_t)bhh * NS + ss) * HDIM + kpos(hd)] = hv;
                    } else {
                        int p = kpos(ss);
                        g_V[((size_t)bhh * HDIM + hd) * NS + p] = __float2half_rn(ca);
                        g_V[((size_t)bhh * HDIM + hd + 1) * NS + p] = __float2half_rn(cb);
                    }
                }
            }
        }
    }
}

// ---------------------------------------------------------------------------
// fp16 flash attention, causal.  (R12 shape — best measured attention.)
// CTA: 128 q-rows of one (b,h); 8 warps, warp owns ONE m16 tile.
// 256 thr, 2 CTAs/SM. 64-key double-buffered cp.async.
// Q frags from global; P register-resident.
// ---------------------------------------------------------------------------
#define FLASH_SMEM 32768

__global__ __launch_bounds__(256, 2) void flash_attn_f16()
{
    extern __shared__ __half smf[];
    const int tid = threadIdx.x, lane = tid & 31, wq = tid >> 5;
    const int g = lane >> 2, t = lane & 3;
    const int bh = blockIdx.y;
    const int qt = (int)gridDim.x - 1 - (int)blockIdx.x;
    const int q0 = qt * 128;
    const int trow = q0 + wq * 16;
    const int xorsw = (g & 1) << 2;

    const __half* Kb = g_K + (size_t)bh * NS * HDIM;
    const __half* Vb = g_V + (size_t)bh * HDIM * NS;

    // ---- Q fragments (direct from global; 4 LDG.128) ----
    uint32_t qf[4][4];
    {
        const __half* p0 = g_Q + ((size_t)bh * NS + trow + g) * HDIM;
        const __half* p1 = g_Q + ((size_t)bh * NS + trow + g + 8) * HDIM;
        uint4 a0 = *(const uint4*)(p0 + t * 8);
        uint4 a1 = *(const uint4*)(p1 + t * 8);
        uint4 b0 = *(const uint4*)(p0 + 32 + t * 8);
        uint4 b1 = *(const uint4*)(p1 + 32 + t * 8);
        qf[0][0]=a0.x; qf[0][1]=a1.x; qf[0][2]=a0.y; qf[0][3]=a1.y;
        qf[1][0]=a0.z; qf[1][1]=a1.z; qf[1][2]=a0.w; qf[1][3]=a1.w;
        qf[2][0]=b0.x; qf[2][1]=b1.x; qf[2][2]=b0.y; qf[2][3]=b1.y;
        qf[3][0]=b0.z; qf[3][1]=b1.z; qf[3][2]=b0.w; qf[3][3]=b1.w;
    }

    auto prefetch = [&](int kt) {
        __half* Ks = smf + (kt & 1) * 4096;
        __half* Vs = smf + 8192 + (kt & 1) * 4096;
        int kk0 = kt * 64;
#pragma unroll
        for (int i = 0; i < 2; i++) {
            int cid = tid + i * 256;       // 0..511
            int row = cid >> 3, c = cid & 7;
            int sw = c ^ ((row & 1) << 2);
            cp16(Ks + row * 64 + sw * 8, Kb + (size_t)(kk0 + row) * HDIM + c * 8);
            cp16(Vs + row * 64 + sw * 8, Vb + (size_t)row * NS + kk0 + c * 8);
        }
    };

    prefetch(0); cp_commit();

    float oacc[8][4];
#pragma unroll
    for (int i = 0; i < 8; i++)
#pragma unroll
        for (int c = 0; c < 4; c++) oacc[i][c] = 0.0f;
    float mx0 = -INFINITY, mx1 = -INFINITY;
    float ls0 = 0.0f, ls1 = 0.0f;

    const int ktmax = 2 * qt + 1;
    for (int kt = 0; kt <= ktmax; kt++) {
        cp_wait0();
        __syncthreads();
        if (kt < ktmax) { prefetch(kt + 1); cp_commit(); }

        const int k0 = kt * 64;
        if (k0 > trow + 15) continue;      // warp-uniform; barrier at loop top
        const __half* Ks = smf + (kt & 1) * 4096;
        const __half* Vs = smf + 8192 + (kt & 1) * 4096;

        // ---- S = Q K^T (k-step outer) ----
        float sacc[8][4];
#pragma unroll
        for (int i = 0; i < 8; i++)
#pragma unroll
            for (int c = 0; c < 4; c++) sacc[i][c] = 0.0f;

#pragma unroll
        for (int nth = 0; nth < 2; nth++) {
            uint4 kb[4][2];
#pragma unroll
            for (int j = 0; j < 4; j++) {
                const __half* rb = Ks + (8 * (nth * 4 + j) + g) * 64;
                kb[j][0] = *(const uint4*)(rb + (t ^ xorsw) * 8);
                kb[j][1] = *(const uint4*)(rb + ((4 + t) ^ xorsw) * 8);
            }
#pragma unroll
            for (int s = 0; s < 4; s++)
#pragma unroll
                for (int j = 0; j < 4; j++) {
                    int nt = nth * 4 + j;
                    uint32_t b0 = (s & 1) ? kb[j][s >> 1].z : kb[j][s >> 1].x;
                    uint32_t b1 = (s & 1) ? kb[j][s >> 1].w : kb[j][s >> 1].y;
                    mma_f16(sacc[nt], qf[s][0], qf[s][1], qf[s][2], qf[s][3],
                            b0, b1);
                }
        }

        // ---- causal mask + online softmax + register P pack ----
        if (k0 + 63 > trow) {
            int r0 = trow + g, r1 = r0 + 8;
#pragma unroll
            for (int nt = 0; nt < 8; nt++) {
                int c0 = k0 + 8 * nt + 2 * t;
                if (c0     > r0) sacc[nt][0] = -INFINITY;
                if (c0 + 1 > r0) sacc[nt][1] = -INFINITY;
                if (c0     > r1) sacc[nt][2] = -INFINITY;
                if (c0 + 1 > r1) sacc[nt][3] = -INFINITY;
            }
        }
        float t0 = -INFINITY, t1 = -INFINITY;
#pragma unroll
        for (int nt = 0; nt < 8; nt++) {
            t0 = fmaxf(t0, fmaxf(sacc[nt][0], sacc[nt][1]));
            t1 = fmaxf(t1, fmaxf(sacc[nt][2], sacc[nt][3]));
        }
        t0 = fmaxf(t0, __shfl_xor_sync(0xffffffffu, t0, 1));
        t0 = fmaxf(t0, __shfl_xor_sync(0xffffffffu, t0, 2));
        t1 = fmaxf(t1, __shfl_xor_sync(0xffffffffu, t1, 1));
        t1 = fmaxf(t1, __shfl_xor_sync(0xffffffffu, t1, 2));
        float nm0 = fmaxf(mx0, t0), nm1 = fmaxf(mx1, t1);
        float corr0 = __expf(mx0 - nm0), corr1 = __expf(mx1 - nm1);

        float ps0 = 0.0f, ps1 = 0.0f;
#pragma unroll
        for (int nt = 0; nt < 8; nt++) {
            float p0 = __expf(sacc[nt][0] - nm0);
            float p1 = __expf(sacc[nt][1] - nm0);
            float p2 = __expf(sacc[nt][2] - nm1);
            float p3 = __expf(sacc[nt][3] - nm1);
            ps0 += p0 + p1; ps1 += p2 + p3;
            sacc[nt][0] = p0; sacc[nt][1] = p1;
            sacc[nt][2] = p2; sacc[nt][3] = p3;
        }
        ps0 += __shfl_xor_sync(0xffffffffu, ps0, 1);
        ps0 += __shfl_xor_sync(0xffffffffu, ps0, 2);
        ps1 += __shfl_xor_sync(0xffffffffu, ps1, 1);
        ps1 += __shfl_xor_sync(0xffffffffu, ps1, 2);
        ls0 = ls0 * corr0 + ps0;
        ls1 = ls1 * corr1 + ps1;
        mx0 = nm0; mx1 = nm1;
#pragma unroll
        for (int nt = 0; nt < 8; nt++) {
            oacc[nt][0] *= corr0; oacc[nt][1] *= corr0;
            oacc[nt][2] *= corr1; oacc[nt][3] *= corr1;
        }
        uint32_t pf[4][4];
#pragma unroll
        for (int s = 0; s < 4; s++) {
            pf[s][0] = h2u(sacc[2*s][0],   sacc[2*s][1]);
            pf[s][1] = h2u(sacc[2*s][2],   sacc[2*s][3]);
            pf[s][2] = h2u(sacc[2*s+1][0], sacc[2*s+1][1]);
            pf[s][3] = h2u(sacc[2*s+1][2], sacc[2*s+1][3]);
        }

        // ---- O += P V (k-step outer) ----
#pragma unroll
        for (int nth = 0; nth < 2; nth++) {
            uint4 vb[4][2];
#pragma unroll
            for (int j = 0; j < 4; j++) {
                const __half* rb = Vs + (8 * (nth * 4 + j) + g) * 64;
                vb[j][0] = *(const uint4*)(rb + (t ^ xorsw) * 8);
                vb[j][1] = *(const uint4*)(rb + ((4 + t) ^ xorsw) * 8);
            }
#pragma unroll
            for (int s = 0; s < 4; s++)
#pragma unroll
                for (int j = 0; j < 4; j++) {
                    int nt = nth * 4 + j;
                    uint32_t b0 = (s & 1) ? vb[j][s >> 1].z : vb[j][s >> 1].x;
                    uint32_t b1 = (s & 1) ? vb[j][s >> 1].w : vb[j][s >> 1].y;
                    mma_f16(oacc[nt], pf[s][0], pf[s][1], pf[s][2], pf[s][3],
                            b0, b1);
                }
        }
    }

    // ---- epilogue: fp16 k'-interleaved g_AO ----
    int b = bh >> 4, h = bh & 15;
    float inv0 = 1.0f / ls0, inv1 = 1.0f / ls1;
    int row0 = trow + g;
    __half* O0 = g_AO + ((size_t)(b * NS + row0)) * ND + h * HDIM;
    __half* O1 = g_AO + ((size_t)(b * NS + row0 + 8)) * ND + h * HDIM;
#pragma unroll
    for (int nt = 0; nt < 8; nt++) {
        int p = kpos(8 * nt + 2 * t);
        *(__half2*)&O0[p] = __halves2half2(
            __float2half_rn(oacc[nt][0] * inv0),
            __float2half_rn(oacc[nt][1] * inv0));
        *(__half2*)&O1[p] = __halves2half2(
            __float2half_rn(oacc[nt][2] * inv1),
            __float2half_rn(oacc[nt][3] * inv1));
    }
}

// ---------------------------------------------------------------------------
extern "C" void kernel_launch(void* const* d_in, const int* in_sizes, int n_in,
                              void* d_out, int out_size)
{
    const float* x    = (const float*)d_in[0];
    const float* wq_w = (const float*)d_in[1];
    const float* wq_b = (const float*)d_in[2];
    const float* wk_w = (const float*)d_in[3];
    const float* wk_b = (const float*)d_in[4];
    const float* wv_w = (const float*)d_in[5];
    const float* wv_b = (const float*)d_in[6];
    const float* wo_w = (const float*)d_in[7];
    const float* wo_b = (const float*)d_in[8];
    float* out = (float*)d_out;

    cudaFuncSetAttribute(gemm_f16, cudaFuncAttributeMaxDynamicSharedMemorySize,
                         GEMM_SMEM);
    cudaFuncSetAttribute(flash_attn_f16,
                         cudaFuncAttributeMaxDynamicSharedMemorySize, FLASH_SMEM);

    prep<<<6144, 256>>>(x, wq_w, wk_w, wv_w, wo_w);

    gemm_f16<<<dim3(24, NM / 128), 128, GEMM_SMEM>>>(
        wq_b, wk_b, wv_b, nullptr, 0, 1, 0);

    flash_attn_f16<<<dim3(NS / 128, NB * NH), 256, FLASH_SMEM>>>();

    gemm_f16<<<dim3(8, NM / 128), 128, GEMM_SMEM>>>(
        wo_b, nullptr, nullptr, out, 1, 0, 0);
}